// round 7
// baseline (speedup 1.0000x reference)
#include <cuda_runtime.h>

#define B_      8
#define SEQ     1024
#define DMODEL  768
#define NHEADS  12
#define HDIM    64

// Scratch (allocation-free: __device__ globals)
__device__ float g_q  [B_*SEQ*DMODEL];       // 25 MB
__device__ float g_kv [B_*SEQ*2*DMODEL];     // 50 MB
__device__ float g_ctx[B_*SEQ*DMODEL];       // 25 MB

typedef unsigned long long ull;

// ---- packed f32x2 helpers (FFMA2: 2x fp32 throughput vs 3-reg FFMA) ----
__device__ __forceinline__ ull pack2(float lo, float hi) {
    ull r;
    asm("mov.b64 %0,{%1,%2};" : "=l"(r)
        : "r"(__float_as_uint(lo)), "r"(__float_as_uint(hi)));
    return r;
}
__device__ __forceinline__ void fma2(ull &acc, ull a, ull b) {
    asm("fma.rn.f32x2 %0,%1,%2,%0;" : "+l"(acc) : "l"(a), "l"(b));
}
__device__ __forceinline__ float2 unpack2(ull v) {
    unsigned lo, hi;
    asm("mov.b64 {%0,%1},%2;" : "=r"(lo), "=r"(hi) : "l"(v));
    return make_float2(__uint_as_float(lo), __uint_as_float(hi));
}

// ============================================================================
// C = alpha * A @ B^T (+bias). A:[M,K] row-major (lda), B:[N,K] row-major (ldb).
// 128x128 block tile, BK=8, 256 threads, 8x8 per-thread tile (8x4 f32x2).
// Double-buffered smem: ONE __syncthreads per K-tile, gmem load of tile i+1
// overlaps compute of tile i.
// Batched over blockIdx.z with zo = z/zdiv, zi = z%zdiv offsets.
// All dims are multiples of the tile for every call here.
// ============================================================================
__global__ __launch_bounds__(256, 2)
void gemm_nt(const float* __restrict__ A, const float* __restrict__ Bm,
             float* __restrict__ C, const float* __restrict__ bias,
             int K, int lda, int ldb, int ldc,
             int zdiv,
             long long sAo, long long sAi,
             long long sBo, long long sBi,
             long long sCo, long long sCi,
             float alpha)
{
    __shared__ float As[2][8][132];
    __shared__ float Bs[2][8][132];

    int z  = blockIdx.z;
    int zo = z / zdiv, zi = z - zo * zdiv;
    A  += zo * sAo + zi * sAi;
    Bm += zo * sBo + zi * sBi;
    C  += zo * sCo + zi * sCi;

    int t    = threadIdx.x;
    int row0 = blockIdx.y << 7;
    int col0 = blockIdx.x << 7;
    int lr   = t >> 1;           // 0..127
    int lk   = (t & 1) << 2;     // 0 or 4

    const float* Ald = A  + (long long)(row0 + lr) * lda + lk;
    const float* Bld = Bm + (long long)(col0 + lr) * ldb + lk;

    int ty = t >> 4, tx = t & 15;

    ull acc[8][4];
    #pragma unroll
    for (int i = 0; i < 8; i++)
        #pragma unroll
        for (int j = 0; j < 4; j++) acc[i][j] = 0ull;

    int nk = K >> 3;

    // prologue: fill buffer 0
    {
        float4 av = *(const float4*)(Ald);
        float4 bv = *(const float4*)(Bld);
        As[0][lk+0][lr] = av.x; As[0][lk+1][lr] = av.y;
        As[0][lk+2][lr] = av.z; As[0][lk+3][lr] = av.w;
        Bs[0][lk+0][lr] = bv.x; Bs[0][lk+1][lr] = bv.y;
        Bs[0][lk+2][lr] = bv.z; Bs[0][lk+3][lr] = bv.w;
    }
    __syncthreads();

    for (int it = 0; it < nk; it++) {
        int cur = it & 1;
        float4 av2, bv2;
        bool more = (it + 1 < nk);
        if (more) {
            av2 = *(const float4*)(Ald + ((it + 1) << 3));
            bv2 = *(const float4*)(Bld + ((it + 1) << 3));
        }

        #pragma unroll
        for (int k = 0; k < 8; k++) {
            float4 a0 = *(const float4*)&As[cur][k][ty << 3];
            float4 a1 = *(const float4*)&As[cur][k][(ty << 3) + 4];
            float4 b0 = *(const float4*)&Bs[cur][k][tx << 3];
            float4 b1 = *(const float4*)&Bs[cur][k][(tx << 3) + 4];
            ull aa[8] = { pack2(a0.x,a0.x), pack2(a0.y,a0.y),
                          pack2(a0.z,a0.z), pack2(a0.w,a0.w),
                          pack2(a1.x,a1.x), pack2(a1.y,a1.y),
                          pack2(a1.z,a1.z), pack2(a1.w,a1.w) };
            ull bb[4] = { pack2(b0.x,b0.y), pack2(b0.z,b0.w),
                          pack2(b1.x,b1.y), pack2(b1.z,b1.w) };
            #pragma unroll
            for (int i = 0; i < 8; i++)
                #pragma unroll
                for (int j = 0; j < 4; j++)
                    fma2(acc[i][j], aa[i], bb[j]);
        }

        if (more) {
            int nxt = cur ^ 1;
            As[nxt][lk+0][lr] = av2.x; As[nxt][lk+1][lr] = av2.y;
            As[nxt][lk+2][lr] = av2.z; As[nxt][lk+3][lr] = av2.w;
            Bs[nxt][lk+0][lr] = bv2.x; Bs[nxt][lk+1][lr] = bv2.y;
            Bs[nxt][lk+2][lr] = bv2.z; Bs[nxt][lk+3][lr] = bv2.w;
            __syncthreads();
        }
    }

    int crow = row0 + (ty << 3);
    int ccol = col0 + (tx << 3);
    #pragma unroll
    for (int i = 0; i < 8; i++) {
        float* cp = C + (long long)(crow + i) * ldc + ccol;
        #pragma unroll
        for (int j = 0; j < 4; j++) {
            float2 p = unpack2(acc[i][j]);
            float r0 = alpha * p.x, r1 = alpha * p.y;
            if (bias) {
                r0 += bias[ccol + (j << 1)];
                r1 += bias[ccol + (j << 1) + 1];
            }
            ((float2*)cp)[j] = make_float2(r0, r1);
        }
    }
}

// ============================================================================
// C = A @ B. A:[M,K] row-major (lda), B:[K,N] row-major (ldb). N = 64 exactly.
// 128x64 block tile, BK=16, 256 threads, 8x4 per-thread tile (8x2 f32x2).
// Double-buffered smem, one barrier per K-tile.
// ============================================================================
__global__ __launch_bounds__(256, 2)
void gemm_nn(const float* __restrict__ A, const float* __restrict__ Bm,
             float* __restrict__ C,
             int K, int lda, int ldb, int ldc,
             int zdiv,
             long long sAo, long long sAi,
             long long sBo, long long sBi,
             long long sCo, long long sCi)
{
    __shared__ float As[2][16][132];
    __shared__ float Bs[2][16][68];

    int z  = blockIdx.z;
    int zo = z / zdiv, zi = z - zo * zdiv;
    A  += zo * sAo + zi * sAi;
    Bm += zo * sBo + zi * sBi;
    C  += zo * sCo + zi * sCi;

    int t    = threadIdx.x;
    int row0 = blockIdx.y << 7;
    int lr   = t >> 1;            // 0..127
    int lk   = (t & 1) << 3;      // 0 or 8
    int bk   = t >> 4;            // 0..15
    int bn   = (t & 15) << 2;     // 0..60

    const float* Ald = A  + (long long)(row0 + lr) * lda + lk;
    const float* Bld = Bm + (long long)bk * ldb + bn;

    int ty = t >> 4, tx = t & 15;

    ull acc[8][2];
    #pragma unroll
    for (int i = 0; i < 8; i++) { acc[i][0] = 0ull; acc[i][1] = 0ull; }

    int nk = K >> 4;

    // prologue: fill buffer 0
    {
        float4 a0 = *(const float4*)(Ald);
        float4 a1 = *(const float4*)(Ald + 4);
        float4 bv = *(const float4*)(Bld);
        As[0][lk+0][lr] = a0.x; As[0][lk+1][lr] = a0.y;
        As[0][lk+2][lr] = a0.z; As[0][lk+3][lr] = a0.w;
        As[0][lk+4][lr] = a1.x; As[0][lk+5][lr] = a1.y;
        As[0][lk+6][lr] = a1.z; As[0][lk+7][lr] = a1.w;
        *(float4*)&Bs[0][bk][bn] = bv;
    }
    __syncthreads();

    for (int it = 0; it < nk; it++) {
        int cur = it & 1;
        float4 a0n, a1n, bvn;
        bool more = (it + 1 < nk);
        if (more) {
            int k0 = (it + 1) << 4;
            a0n = *(const float4*)(Ald + k0);
            a1n = *(const float4*)(Ald + k0 + 4);
            bvn = *(const float4*)(Bld + (long long)k0 * ldb);
        }

        #pragma unroll
        for (int k = 0; k < 16; k++) {
            float4 x0 = *(const float4*)&As[cur][k][ty << 3];
            float4 x1 = *(const float4*)&As[cur][k][(ty << 3) + 4];
            float4 y  = *(const float4*)&Bs[cur][k][tx << 2];
            ull aa[8] = { pack2(x0.x,x0.x), pack2(x0.y,x0.y),
                          pack2(x0.z,x0.z), pack2(x0.w,x0.w),
                          pack2(x1.x,x1.x), pack2(x1.y,x1.y),
                          pack2(x1.z,x1.z), pack2(x1.w,x1.w) };
            ull bb[2] = { pack2(y.x,y.y), pack2(y.z,y.w) };
            #pragma unroll
            for (int i = 0; i < 8; i++) {
                fma2(acc[i][0], aa[i], bb[0]);
                fma2(acc[i][1], aa[i], bb[1]);
            }
        }

        if (more) {
            int nxt = cur ^ 1;
            As[nxt][lk+0][lr] = a0n.x; As[nxt][lk+1][lr] = a0n.y;
            As[nxt][lk+2][lr] = a0n.z; As[nxt][lk+3][lr] = a0n.w;
            As[nxt][lk+4][lr] = a1n.x; As[nxt][lk+5][lr] = a1n.y;
            As[nxt][lk+6][lr] = a1n.z; As[nxt][lk+7][lr] = a1n.w;
            *(float4*)&Bs[nxt][bk][bn] = bvn;
            __syncthreads();
        }
    }

    int crow = row0 + (ty << 3);
    int ccol = tx << 2;
    #pragma unroll
    for (int i = 0; i < 8; i++) {
        float* cp = C + (long long)(crow + i) * ldc + ccol;
        float2 p0 = unpack2(acc[i][0]);
        float2 p1 = unpack2(acc[i][1]);
        ((float2*)cp)[0] = p0;
        ((float2*)cp)[1] = p1;
    }
}

// ============================================================================
// In-place softmax over rows of 1024. One 256-thread block per row.
// ============================================================================
__global__ void softmax_rows(float* __restrict__ attn)
{
    float* p = attn + (long long)blockIdx.x * SEQ;
    int t = threadIdx.x;
    float4 v = ((float4*)p)[t];

    __shared__ float red[8];

    float m = fmaxf(fmaxf(v.x, v.y), fmaxf(v.z, v.w));
    #pragma unroll
    for (int o = 16; o > 0; o >>= 1)
        m = fmaxf(m, __shfl_xor_sync(0xffffffffu, m, o));
    if ((t & 31) == 0) red[t >> 5] = m;
    __syncthreads();
    float bm = red[0];
    #pragma unroll
    for (int i = 1; i < 8; i++) bm = fmaxf(bm, red[i]);

    float e0 = expf(v.x - bm), e1 = expf(v.y - bm);
    float e2 = expf(v.z - bm), e3 = expf(v.w - bm);
    float s = (e0 + e1) + (e2 + e3);
    #pragma unroll
    for (int o = 16; o > 0; o >>= 1)
        s += __shfl_xor_sync(0xffffffffu, s, o);
    __syncthreads();              // protect red[] reuse
    if ((t & 31) == 0) red[t >> 5] = s;
    __syncthreads();
    float bs = red[0];
    #pragma unroll
    for (int i = 1; i < 8; i++) bs += red[i];

    float inv = 1.0f / bs;
    ((float4*)p)[t] = make_float4(e0 * inv, e1 * inv, e2 * inv, e3 * inv);
}

// ============================================================================
// d_in: 0=x [8,1024,768] f32, 1=q_w [768,768], 2=kv_w [1536,768],
//       3=proj_w [768,768], 4=proj_b [768], 5=H(int), 6=W(int)
// d_out: out [8*1024*768] f32 followed by attn [8*12*1024*1024] f32
// ============================================================================
extern "C" void kernel_launch(void* const* d_in, const int* in_sizes, int n_in,
                              void* d_out, int out_size)
{
    const float* x   = (const float*)d_in[0];
    const float* qw  = (const float*)d_in[1];
    const float* kvw = (const float*)d_in[2];
    const float* pw  = (const float*)d_in[3];
    const float* pb  = (const float*)d_in[4];

    float* out  = (float*)d_out;
    float* attn = out + (long long)B_ * SEQ * DMODEL;

    float *gq, *gkv, *gctx;
    cudaGetSymbolAddress((void**)&gq,   g_q);
    cudaGetSymbolAddress((void**)&gkv,  g_kv);
    cudaGetSymbolAddress((void**)&gctx, g_ctx);

    const float scale = 0.125f;   // 64^-0.5
    const int   MROWS = B_ * SEQ; // 8192

    // 1) Q = x @ q_w^T        [8192, 768]
    gemm_nt<<<dim3(DMODEL / 128, MROWS / 128, 1), 256>>>(
        x, qw, gq, nullptr,
        DMODEL, DMODEL, DMODEL, DMODEL,
        1, 0, 0, 0, 0, 0, 0, 1.0f);

    // 2) KV = x @ kv_w^T      [8192, 1536]
    gemm_nt<<<dim3(2 * DMODEL / 128, MROWS / 128, 1), 256>>>(
        x, kvw, gkv, nullptr,
        DMODEL, DMODEL, DMODEL, 2 * DMODEL,
        1, 0, 0, 0, 0, 0, 0, 1.0f);

    // 3) S[b,h] = scale * Q_h @ K_h^T   (96 batched [1024,1024,64] GEMMs)
    //    K rows live in g_kv at s=0: base + b*SEQ*1536 + h*64, ld 1536
    gemm_nt<<<dim3(SEQ / 128, SEQ / 128, B_ * NHEADS), 256>>>(
        gq, gkv, attn, nullptr,
        HDIM, DMODEL, 2 * DMODEL, SEQ,
        NHEADS,
        (long long)SEQ * DMODEL,      HDIM,   // A: per-b, per-h
        (long long)SEQ * 2 * DMODEL,  HDIM,   // B: per-b, per-h
        (long long)NHEADS * SEQ * SEQ, (long long)SEQ * SEQ,  // C
        scale);

    // 4) row softmax in place (98304 rows)
    softmax_rows<<<B_ * NHEADS * SEQ, 256>>>(attn);

    // 5) ctx[b,:,h*64:...] = attn[b,h] @ V_h   (V at s=1: +768 within row)
    gemm_nn<<<dim3(1, SEQ / 128, B_ * NHEADS), 256>>>(
        attn, gkv + DMODEL, gctx,
        SEQ, SEQ, 2 * DMODEL, DMODEL,
        NHEADS,
        (long long)NHEADS * SEQ * SEQ, (long long)SEQ * SEQ,  // A
        (long long)SEQ * 2 * DMODEL,   HDIM,                  // B
        (long long)SEQ * DMODEL,       HDIM);                 // C

    // 6) out = ctx @ proj_w^T + proj_b
    gemm_nt<<<dim3(DMODEL / 128, MROWS / 128, 1), 256>>>(
        gctx, pw, out, pb,
        DMODEL, DMODEL, DMODEL, DMODEL,
        1, 0, 0, 0, 0, 0, 0, 1.0f);
}

// round 9
// speedup vs baseline: 1.6813x; 1.6813x over previous
#include <cuda_runtime.h>
#include <cstdint>

#define B_      8
#define SEQ     1024
#define DMODEL  768
#define NHEADS  12
#define HDIM    64

// Scratch (allocation-free: __device__ globals)
__device__ float g_q  [B_*SEQ*DMODEL];            // 25 MB
__device__ float g_kv [B_*SEQ*2*DMODEL];          // 50 MB
__device__ float g_ctx[B_*SEQ*DMODEL];            // 25 MB
__device__ float g_vt [B_*NHEADS*HDIM*SEQ];       // 25 MB  V^T per (b,h): [64][1024]

// ---------------------------------------------------------------------------
// helpers
// ---------------------------------------------------------------------------
__device__ __forceinline__ uint32_t smem_u32(const void* p) {
    uint32_t a;
    asm("{ .reg .u64 t; cvta.to.shared.u64 t, %1; cvt.u32.u64 %0, t; }"
        : "=r"(a) : "l"(p));
    return a;
}

// cvt.rn.bf16x2.f32 d, hi, lo  ->  d.lo = bf16(lo-arg), d.hi = bf16(hi-arg)
__device__ __forceinline__ uint32_t pack_bf2(float a, float b) {
    uint32_t r;
    asm("cvt.rn.bf16x2.f32 %0, %1, %2;" : "=r"(r) : "f"(b), "f"(a));
    return r;
}

// 8 fp32 -> 8 bf16 hi + 8 bf16 residual lo
__device__ __forceinline__ void cvt8(float4 f0, float4 f1, uint4& hv, uint4& lv) {
    uint32_t h0 = pack_bf2(f0.x, f0.y);
    uint32_t h1 = pack_bf2(f0.z, f0.w);
    uint32_t h2 = pack_bf2(f1.x, f1.y);
    uint32_t h3 = pack_bf2(f1.z, f1.w);
    hv = make_uint4(h0, h1, h2, h3);
    float r0 = f0.x - __uint_as_float(h0 << 16);
    float r1 = f0.y - __uint_as_float(h0 & 0xffff0000u);
    float r2 = f0.z - __uint_as_float(h1 << 16);
    float r3 = f0.w - __uint_as_float(h1 & 0xffff0000u);
    float r4 = f1.x - __uint_as_float(h2 << 16);
    float r5 = f1.y - __uint_as_float(h2 & 0xffff0000u);
    float r6 = f1.z - __uint_as_float(h3 << 16);
    float r7 = f1.w - __uint_as_float(h3 & 0xffff0000u);
    lv = make_uint4(pack_bf2(r0, r1), pack_bf2(r2, r3),
                    pack_bf2(r4, r5), pack_bf2(r6, r7));
}

__device__ __forceinline__ void ldsm4(uint32_t addr, uint32_t* r) {
    asm volatile("ldmatrix.sync.aligned.m8n8.x4.shared.b16 {%0,%1,%2,%3}, [%4];"
        : "=r"(r[0]), "=r"(r[1]), "=r"(r[2]), "=r"(r[3]) : "r"(addr));
}

__device__ __forceinline__ void mma16816(float* d, const uint32_t* a, const uint32_t* b) {
    asm volatile(
        "mma.sync.aligned.m16n8k16.row.col.f32.bf16.bf16.f32 "
        "{%0,%1,%2,%3},{%4,%5,%6,%7},{%8,%9},{%0,%1,%2,%3};"
        : "+f"(d[0]), "+f"(d[1]), "+f"(d[2]), "+f"(d[3])
        : "r"(a[0]), "r"(a[1]), "r"(a[2]), "r"(a[3]), "r"(b[0]), "r"(b[1]));
}

// ---------------------------------------------------------------------------
// HMMA GEMM: C[128,BN] = alpha * (A @ B^T) (+bias).
// A:[M,K] fp32 row-major (lda), B:[N,K] fp32 row-major (ldb).
// fp32 -> bf16-pair on smem fill; 3 MMAs (hh, hl, lh) per m16n8k16 tile.
// K multiple of 32. 512 threads. BN in {64, 128}.
// smem rows: 32 bf16 = 64 B = 4 x 16B chunks, swizzle chunk ^ (row & 3).
// ---------------------------------------------------------------------------
template <int BN>
__global__ void __launch_bounds__(512)
gemm_hmma(const float* __restrict__ A, const float* __restrict__ Bm,
          float* __restrict__ C, const float* __restrict__ bias,
          int K, int lda, int ldb, int ldc,
          int zdiv,
          long long sAo, long long sAi,
          long long sBo, long long sBi,
          long long sCo, long long sCi,
          float alpha)
{
    extern __shared__ char smem[];
    const int ASZ = 128 * 64;          // bytes: A bf16 tile (128 rows x 64 B)
    const int BSZ = BN * 64;
    const int STG = 2 * ASZ + 2 * BSZ; // AH | AL | BH | BL
    const int WN  = BN / 4;            // warp n-width: 32 or 16
    const int NT  = WN / 8;            // n8 tiles per warp: 4 or 2

    int z  = blockIdx.z;
    int zo = z / zdiv, zi = z - zo * zdiv;
    A  += zo * sAo + zi * sAi;
    Bm += zo * sBo + zi * sBi;
    C  += zo * sCo + zi * sCi;

    int t    = threadIdx.x;
    int warp = t >> 5, lane = t & 31;
    int wm   = warp >> 2, wn = warp & 3;

    int row0 = blockIdx.y << 7;
    int col0 = blockIdx.x * BN;

    // fill roles: thread t handles (row = t>>2, 16B chunk = t&3)
    int frow = t >> 2, fc = t & 3;
    uint32_t foff = (uint32_t)frow * 64 + ((fc ^ (frow & 3)) << 4);
    const float* Asrc = A + (long long)(row0 + frow) * lda + fc * 8;
    const bool bact = (BN == 128) || (t < BN * 4);
    const float* Bsrc = Bm + (long long)(col0 + frow) * ldb + fc * 8;

    uint32_t sb = smem_u32(smem);

    float acc[2][NT][4];
    #pragma unroll
    for (int i = 0; i < 2; i++)
        #pragma unroll
        for (int j = 0; j < NT; j++)
            #pragma unroll
            for (int q = 0; q < 4; q++) acc[i][j][q] = 0.0f;

    int nk = K >> 5;

    // prologue: fill stage 0
    {
        float4 a0 = *(const float4*)(Asrc);
        float4 a1 = *(const float4*)(Asrc + 4);
        uint4 hv, lv;
        cvt8(a0, a1, hv, lv);
        *(uint4*)(smem + foff)       = hv;
        *(uint4*)(smem + ASZ + foff) = lv;
        if (bact) {
            float4 b0 = *(const float4*)(Bsrc);
            float4 b1 = *(const float4*)(Bsrc + 4);
            cvt8(b0, b1, hv, lv);
            *(uint4*)(smem + 2 * ASZ + foff)       = hv;
            *(uint4*)(smem + 2 * ASZ + BSZ + foff) = lv;
        }
    }
    __syncthreads();

    // ldmatrix address components (constant across stages)
    int arow_base = wm * 32 + (lane & 15);        // + mi*16
    int asel      = lane >> 4;                    // k half (chunk +0/+1)
    int nrow_base = wn * WN + (lane & 7) + ((lane >> 4) << 3);  // + p*16
    int bsel      = (lane >> 3) & 1;

    for (int it = 0; it < nk; it++) {
        int cur = it & 1;
        bool more = (it + 1 < nk);
        float4 la0, la1, lb0, lb1;
        if (more) {
            int k0 = (it + 1) << 5;
            la0 = *(const float4*)(Asrc + k0);
            la1 = *(const float4*)(Asrc + k0 + 4);
            if (bact) {
                lb0 = *(const float4*)(Bsrc + k0);
                lb1 = *(const float4*)(Bsrc + k0 + 4);
            }
        }

        uint32_t sA = sb + cur * STG;
        uint32_t sB = sA + 2 * ASZ;

        #pragma unroll
        for (int ks = 0; ks < 2; ks++) {
            uint32_t ah[2][4], al[2][4];
            #pragma unroll
            for (int mi = 0; mi < 2; mi++) {
                int r = arow_base + mi * 16;
                uint32_t ch = (uint32_t)(ks * 2 + asel) ^ (r & 3);
                uint32_t off = (uint32_t)r * 64 + (ch << 4);
                ldsm4(sA + off, ah[mi]);
                ldsm4(sA + ASZ + off, al[mi]);
            }
            uint32_t bh[NT][2], bl[NT][2];
            #pragma unroll
            for (int p = 0; p < NT / 2; p++) {
                int n = nrow_base + p * 16;
                uint32_t ch = (uint32_t)(ks * 2 + bsel) ^ (n & 3);
                uint32_t off = (uint32_t)n * 64 + (ch << 4);
                uint32_t rh[4], rl[4];
                ldsm4(sB + off, rh);
                ldsm4(sB + BSZ + off, rl);
                bh[2 * p][0] = rh[0]; bh[2 * p][1] = rh[1];
                bh[2 * p + 1][0] = rh[2]; bh[2 * p + 1][1] = rh[3];
                bl[2 * p][0] = rl[0]; bl[2 * p][1] = rl[1];
                bl[2 * p + 1][0] = rl[2]; bl[2 * p + 1][1] = rl[3];
            }
            #pragma unroll
            for (int mi = 0; mi < 2; mi++)
                #pragma unroll
                for (int ni = 0; ni < NT; ni++) {
                    mma16816(acc[mi][ni], ah[mi], bh[ni]);
                    mma16816(acc[mi][ni], ah[mi], bl[ni]);
                    mma16816(acc[mi][ni], al[mi], bh[ni]);
                }
        }

        if (more) {
            int nxt = cur ^ 1;
            char* st = smem + nxt * STG;
            uint4 hv, lv;
            cvt8(la0, la1, hv, lv);
            *(uint4*)(st + foff)       = hv;
            *(uint4*)(st + ASZ + foff) = lv;
            if (bact) {
                cvt8(lb0, lb1, hv, lv);
                *(uint4*)(st + 2 * ASZ + foff)       = hv;
                *(uint4*)(st + 2 * ASZ + BSZ + foff) = lv;
            }
        }
        __syncthreads();
    }

    // epilogue: c0,c1 -> (row, col..col+1); c2,c3 -> (row+8, same cols)
    #pragma unroll
    for (int mi = 0; mi < 2; mi++) {
        int r = row0 + wm * 32 + mi * 16 + (lane >> 2);
        #pragma unroll
        for (int ni = 0; ni < NT; ni++) {
            int cidx = col0 + wn * WN + ni * 8 + (lane & 3) * 2;
            float b0 = 0.f, b1 = 0.f;
            if (bias) { b0 = bias[cidx]; b1 = bias[cidx + 1]; }
            float* cp = C + (long long)r * ldc + cidx;
            *(float2*)cp = make_float2(acc[mi][ni][0] * alpha + b0,
                                       acc[mi][ni][1] * alpha + b1);
            cp += 8 * ldc;
            *(float2*)cp = make_float2(acc[mi][ni][2] * alpha + b0,
                                       acc[mi][ni][3] * alpha + b1);
        }
    }
}

// ---------------------------------------------------------------------------
// Transpose V half of kv into g_vt[(b*12+h)*64 + d][tok]  (64x64 smem tiles)
// ---------------------------------------------------------------------------
__global__ void __launch_bounds__(256)
transpose_v(const float* __restrict__ kv, float* __restrict__ vt)
{
    __shared__ float s[64][65];
    int bh = blockIdx.x;
    int b = bh / NHEADS, h = bh - b * NHEADS;
    int tk = blockIdx.y << 6;
    int t = threadIdx.x;
    int tl = t >> 2;             // 0..63
    int ds = (t & 3) << 4;       // 0,16,32,48

    const float* src = kv + ((long long)(b * SEQ + tk + tl)) * (2 * DMODEL)
                          + DMODEL + h * HDIM + ds;
    #pragma unroll
    for (int j = 0; j < 16; j += 4) {
        float4 v = *(const float4*)(src + j);
        s[tl][ds + j + 0] = v.x; s[tl][ds + j + 1] = v.y;
        s[tl][ds + j + 2] = v.z; s[tl][ds + j + 3] = v.w;
    }
    __syncthreads();

    int dl = t >> 2;
    int ts = (t & 3) << 4;
    float* dst = vt + ((long long)(bh * HDIM + dl)) * SEQ + tk + ts;
    #pragma unroll
    for (int j = 0; j < 16; j += 4) {
        float4 v;
        v.x = s[ts + j + 0][dl]; v.y = s[ts + j + 1][dl];
        v.z = s[ts + j + 2][dl]; v.w = s[ts + j + 3][dl];
        *(float4*)(dst + j) = v;
    }
}

// ---------------------------------------------------------------------------
// In-place softmax over rows of 1024. One 256-thread block per row.
// ---------------------------------------------------------------------------
__global__ void softmax_rows(float* __restrict__ attn)
{
    float* p = attn + (long long)blockIdx.x * SEQ;
    int t = threadIdx.x;
    float4 v = ((float4*)p)[t];

    __shared__ float red[8];

    float m = fmaxf(fmaxf(v.x, v.y), fmaxf(v.z, v.w));
    #pragma unroll
    for (int o = 16; o > 0; o >>= 1)
        m = fmaxf(m, __shfl_xor_sync(0xffffffffu, m, o));
    if ((t & 31) == 0) red[t >> 5] = m;
    __syncthreads();
    float bm = red[0];
    #pragma unroll
    for (int i = 1; i < 8; i++) bm = fmaxf(bm, red[i]);

    float e0 = expf(v.x - bm), e1 = expf(v.y - bm);
    float e2 = expf(v.z - bm), e3 = expf(v.w - bm);
    float s = (e0 + e1) + (e2 + e3);
    #pragma unroll
    for (int o = 16; o > 0; o >>= 1)
        s += __shfl_xor_sync(0xffffffffu, s, o);
    __syncthreads();
    if ((t & 31) == 0) red[t >> 5] = s;
    __syncthreads();
    float bs = red[0];
    #pragma unroll
    for (int i = 1; i < 8; i++) bs += red[i];

    float inv = 1.0f / bs;
    ((float4*)p)[t] = make_float4(e0 * inv, e1 * inv, e2 * inv, e3 * inv);
}

// ---------------------------------------------------------------------------
// d_in: 0=x [8,1024,768] f32, 1=q_w [768,768], 2=kv_w [1536,768],
//       3=proj_w [768,768], 4=proj_b [768], 5=H, 6=W
// d_out: out [8*1024*768] f32 followed by attn [8*12*1024*1024] f32
// ---------------------------------------------------------------------------
extern "C" void kernel_launch(void* const* d_in, const int* in_sizes, int n_in,
                              void* d_out, int out_size)
{
    const float* x   = (const float*)d_in[0];
    const float* qw  = (const float*)d_in[1];
    const float* kvw = (const float*)d_in[2];
    const float* pw  = (const float*)d_in[3];
    const float* pb  = (const float*)d_in[4];

    float* out  = (float*)d_out;
    float* attn = out + (long long)B_ * SEQ * DMODEL;

    float *gq, *gkv, *gctx, *gvt;
    cudaGetSymbolAddress((void**)&gq,   g_q);
    cudaGetSymbolAddress((void**)&gkv,  g_kv);
    cudaGetSymbolAddress((void**)&gctx, g_ctx);
    cudaGetSymbolAddress((void**)&gvt,  g_vt);

    // dynamic smem: 2 stages * (AH+AL+BH+BL)
    const int SMEM128 = 2 * (2 * 128 * 64 + 2 * 128 * 64);  // 65536
    const int SMEM64  = 2 * (2 * 128 * 64 + 2 * 64 * 64);   // 49152
    cudaFuncSetAttribute(gemm_hmma<128>, cudaFuncAttributeMaxDynamicSharedMemorySize, SMEM128);
    cudaFuncSetAttribute(gemm_hmma<64>,  cudaFuncAttributeMaxDynamicSharedMemorySize, SMEM64);

    const int MROWS = B_ * SEQ;                 // 8192
    const long long SS = (long long)SEQ * SEQ;

    // 1) Q = x @ q_w^T           [8192, 768]
    gemm_hmma<128><<<dim3(DMODEL / 128, MROWS / 128, 1), 512, SMEM128>>>(
        x, qw, gq, nullptr,
        DMODEL, DMODEL, DMODEL, DMODEL,
        1, 0, 0, 0, 0, 0, 0, 1.0f);

    // 2) KV = x @ kv_w^T         [8192, 1536]
    gemm_hmma<128><<<dim3(2 * DMODEL / 128, MROWS / 128, 1), 512, SMEM128>>>(
        x, kvw, gkv, nullptr,
        DMODEL, DMODEL, DMODEL, 2 * DMODEL,
        1, 0, 0, 0, 0, 0, 0, 1.0f);

    // 2b) V^T per (b,h)
    transpose_v<<<dim3(B_ * NHEADS, SEQ / 64, 1), 256>>>(gkv, gvt);

    // 3) S[b,h] = 0.125 * Q_h @ K_h^T   (96 batched [1024,1024,64])
    gemm_hmma<128><<<dim3(SEQ / 128, SEQ / 128, B_ * NHEADS), 512, SMEM128>>>(
        gq, gkv, attn, nullptr,
        HDIM, DMODEL, 2 * DMODEL, SEQ,
        NHEADS,
        (long long)SEQ * DMODEL,     HDIM,        // A: per-b, per-h
        (long long)SEQ * 2 * DMODEL, HDIM,        // B (K half of kv)
        (long long)NHEADS * SS,      SS,          // C
        0.125f);

    // 4) row softmax in place
    softmax_rows<<<B_ * NHEADS * SEQ, 256>>>(attn);

    // 5) ctx[b,:,h*64..] = attn[b,h] @ Vt[b,h]^T   (NT with B = V^T [64,1024])
    gemm_hmma<64><<<dim3(1, SEQ / 128, B_ * NHEADS), 512, SMEM64>>>(
        attn, gvt, gctx, nullptr,
        SEQ, SEQ, SEQ, DMODEL,
        NHEADS,
        (long long)NHEADS * SS,          SS,                     // A
        (long long)NHEADS * HDIM * SEQ,  (long long)HDIM * SEQ,  // B
        (long long)SEQ * DMODEL,         HDIM,                   // C
        1.0f);

    // 6) out = ctx @ proj_w^T + proj_b
    gemm_hmma<128><<<dim3(DMODEL / 128, MROWS / 128, 1), 512, SMEM128>>>(
        gctx, pw, out, pb,
        DMODEL, DMODEL, DMODEL, DMODEL,
        1, 0, 0, 0, 0, 0, 0, 1.0f);
}